// round 5
// baseline (speedup 1.0000x reference)
#include <cuda_runtime.h>
#include <cuda_bf16.h>
#include <cstdint>

// Problem constants (shapes fixed by the reference).
#define N_NODES 100000
#define N_FEAT  64   // both N_IN and N_OUT

// Scratch for h = X @ W  (25.6 MB). __device__ global => allocation-free.
// Referenced directly from device code; no cudaGetSymbolAddress needed.
__device__ float g_h[(size_t)N_NODES * N_FEAT];

// -----------------------------------------------------------------------------
// Kernel 1: h = X @ W.   W cached in shared, X-row loads broadcast within warp.
// Block = (64, 4): 4 node-rows per block, 64 output cols per row.
// -----------------------------------------------------------------------------
__global__ void __launch_bounds__(256) gemm_xw_kernel(
    const float* __restrict__ X, const float* __restrict__ W, int n_nodes)
{
    __shared__ float Ws[N_FEAT][N_FEAT + 1];   // +1 pad: conflict-free column reads
    const int col = threadIdx.x;               // 0..63
    const int ry  = threadIdx.y;               // 0..3

    // Cooperative load of W (64x64) into shared.
    #pragma unroll
    for (int k = ry; k < N_FEAT; k += 4)
        Ws[k][col] = W[k * N_FEAT + col];
    __syncthreads();

    const int row = blockIdx.x * 4 + ry;
    if (row >= n_nodes) return;

    const float4* xrow = reinterpret_cast<const float4*>(X + (size_t)row * N_FEAT);
    float sum = 0.0f;
    #pragma unroll
    for (int k4 = 0; k4 < N_FEAT / 4; ++k4) {
        // Uniform across the warp (same row) -> broadcast, L1-hit after first lane.
        const float4 x = xrow[k4];
        sum = fmaf(x.x, Ws[4 * k4 + 0][col], sum);
        sum = fmaf(x.y, Ws[4 * k4 + 1][col], sum);
        sum = fmaf(x.z, Ws[4 * k4 + 2][col], sum);
        sum = fmaf(x.w, Ws[4 * k4 + 3][col], sum);
    }
    g_h[(size_t)row * N_FEAT + col] = sum;
}

// -----------------------------------------------------------------------------
// Kernel 2: edge scatter. 16 lanes per edge; each lane handles 4 channels via
// float4 gather from h and red.global.add.v4.f32 (no-return atomic) to out.
// Per edge: one coalesced 256B read + one coalesced 256B vector-reduction.
// -----------------------------------------------------------------------------
__global__ void __launch_bounds__(256) scatter_edges_kernel(
    const float* __restrict__ edge_val,
    const int*   __restrict__ edge_src,
    const int*   __restrict__ edge_dst,
    float*       __restrict__ out,
    int n_edges)
{
    const int t    = blockIdx.x * blockDim.x + threadIdx.x;
    const int e    = t >> 4;          // edge index (16 lanes per edge)
    const int lane = t & 15;          // channel group 0..15 (4 floats each)
    if (e >= n_edges) return;

    // Edge metadata: uniform within each half-warp -> broadcast sectors.
    const int   s = edge_src[e];
    const int   d = edge_dst[e];
    const float v = edge_val[e];

    const float4 h = reinterpret_cast<const float4*>(g_h + (size_t)s * N_FEAT)[lane];
    const float mx = h.x * v, my = h.y * v, mz = h.z * v, mw = h.w * v;

    float* p = out + (size_t)d * N_FEAT + lane * 4;   // 16B-aligned
    asm volatile("red.global.add.v4.f32 [%0], {%1, %2, %3, %4};"
                 :: "l"(p), "f"(mx), "f"(my), "f"(mz), "f"(mw)
                 : "memory");
}

// -----------------------------------------------------------------------------
// Kernel 3: in-place ReLU epilogue over out (float4 vectorized).
// -----------------------------------------------------------------------------
__global__ void __launch_bounds__(256) relu_kernel(float* __restrict__ out, int n4)
{
    const int i = blockIdx.x * blockDim.x + threadIdx.x;
    if (i >= n4) return;
    float4 v = reinterpret_cast<float4*>(out)[i];
    v.x = fmaxf(v.x, 0.0f);
    v.y = fmaxf(v.y, 0.0f);
    v.z = fmaxf(v.z, 0.0f);
    v.w = fmaxf(v.w, 0.0f);
    reinterpret_cast<float4*>(out)[i] = v;
}

// -----------------------------------------------------------------------------
// Launch: memset(out) -> gemm -> scatter -> relu, all on the default stream
// (sequential dependencies), fully graph-capturable. Only memset + kernel
// launches — no other runtime API calls during capture.
// Input order (metadata): X, W, edge_val, edge_src, edge_dst.
// -----------------------------------------------------------------------------
extern "C" void kernel_launch(void* const* d_in, const int* in_sizes, int n_in,
                              void* d_out, int out_size)
{
    const float* X        = (const float*)d_in[0];
    const float* W        = (const float*)d_in[1];
    const float* edge_val = (const float*)d_in[2];
    const int*   edge_src = (const int*)  d_in[3];
    const int*   edge_dst = (const int*)  d_in[4];
    float*       out      = (float*)d_out;

    const int n_nodes = in_sizes[0] / N_FEAT;   // 100000
    const int n_edges = in_sizes[2];            // 1600000

    // Zero the accumulation buffer (d_out is poisoned by the harness).
    cudaMemsetAsync(d_out, 0, (size_t)out_size * sizeof(float), 0);

    // 1) h = X @ W
    {
        dim3 block(64, 4);
        int grid = (n_nodes + 3) / 4;
        gemm_xw_kernel<<<grid, block>>>(X, W, n_nodes);
    }

    // 2) scatter-add over edges (16 lanes per edge)
    {
        const long long total = (long long)n_edges * 16;
        int grid = (int)((total + 255) / 256);
        scatter_edges_kernel<<<grid, 256>>>(edge_val, edge_src, edge_dst,
                                            out, n_edges);
    }

    // 3) ReLU epilogue
    {
        const int n4 = (n_nodes * N_FEAT) / 4;
        int grid = (n4 + 255) / 256;
        relu_kernel<<<grid, 256>>>(out, n4);
    }
}